// round 6
// baseline (speedup 1.0000x reference)
#include <cuda_runtime.h>

#define HH 512
#define WW 512
#define CHN 6
#define BATCH 2
#define EPS_F 1e-6f

typedef unsigned long long ull;

// ---------- f32x2 packed helpers (sm_100+/sm_103a) ----------
__device__ __forceinline__ ull f2pk(float lo, float hi) {
    ull r;
    asm("mov.b64 %0, {%1, %2};" : "=l"(r) : "f"(lo), "f"(hi));
    return r;
}
__device__ __forceinline__ void f2up(ull v, float& lo, float& hi) {
    asm("mov.b64 {%0, %1}, %2;" : "=f"(lo), "=f"(hi) : "l"(v));
}
__device__ __forceinline__ ull f2fma(ull a, ull b, ull c) {
    ull d;
    asm("fma.rn.f32x2 %0, %1, %2, %3;" : "=l"(d) : "l"(a), "l"(b), "l"(c));
    return d;
}
__device__ __forceinline__ ull f2add(ull a, ull b) {
    ull d;
    asm("add.rn.f32x2 %0, %1, %2;" : "=l"(d) : "l"(a), "l"(b));
    return d;
}
__device__ __forceinline__ ull f2mul(ull a, ull b) {
    ull d;
    asm("mul.rn.f32x2 %0, %1, %2;" : "=l"(d) : "l"(a), "l"(b));
    return d;
}
__device__ __forceinline__ ull f2swap(ull v) {
    float lo, hi;
    f2up(v, lo, hi);
    return f2pk(hi, lo);
}

#define NEG1_F2 0xBF800000BF800000ULL  // (-1.0f, -1.0f)

__device__ __forceinline__ int refl(int i, int n) {
    if (i < 0) i = -i;
    if (i >= n) i = 2 * n - 2 - i;
    return i;
}

// upper-triangle (i<=j) linear index into 21-entry array
__device__ __forceinline__ constexpr int IU(int i, int j) {
    return i * 6 - i * (i - 1) / 2 + (j - i);
}
// lower-triangle (i>=j) linear index into 21-entry array
__device__ __forceinline__ constexpr int IL(int i, int j) {
    return i * (i + 1) / 2 + j;
}
// strict upper (i<j) linear index into 15-entry array
__device__ __forceinline__ constexpr int IP(int i, int j) {
    return i * 5 - i * (i - 1) / 2 + (j - i - 1);
}

// Per-pixel CCA from packed window sums.
// s2q[21]: (sxx, syy) upper-tri. s2c[15]: (sxy[i][j], sxy[j][i]) i<j.
// sd[6]: sxy diagonal. s2s[6]: (sx, sy).
__device__ __forceinline__ float cca6(const ull* s2s, const ull* s2q,
                                      const ull* s2c, const float* sd,
                                      float inv_n) {
    const ull NEG1 = NEG1_F2;
    const ull INVN2 = f2pk(inv_n, inv_n);
    const ull EPS2 = f2pk(EPS_F, EPS_F);

    ull m2[6], nm2[6];
#pragma unroll
    for (int i = 0; i < 6; i++) {
        m2[i] = f2mul(s2s[i], INVN2);
        nm2[i] = f2mul(m2[i], NEG1);
    }

    // Packed Cholesky of (Cxx, Cyy): L2[t] = (Lx[t], Ly[t])
    ull L2[21], iv2[6];
#pragma unroll
    for (int j = 0; j < 6; j++) {
        ull d2 = f2fma(nm2[j], m2[j], f2mul(s2q[IU(j, j)], INVN2));
        d2 = f2add(d2, EPS2);
        if (j > 0) {
            ull acc = f2mul(L2[IL(j, 0)], L2[IL(j, 0)]);
#pragma unroll
            for (int t = 1; t < j; t++) acc = f2fma(L2[IL(j, t)], L2[IL(j, t)], acc);
            d2 = f2fma(acc, NEG1, d2);
        }
        float dx, dy;
        f2up(d2, dx, dy);
        float rx = rsqrtf(dx), ry = rsqrtf(dy);
        iv2[j] = f2pk(rx, ry);
        L2[IL(j, j)] = f2mul(d2, iv2[j]);
#pragma unroll
        for (int i = j + 1; i < 6; i++) {
            ull v2 = f2fma(nm2[j], m2[i], f2mul(s2q[IU(j, i)], INVN2));
            if (j > 0) {
                ull acc = f2mul(L2[IL(i, 0)], L2[IL(j, 0)]);
#pragma unroll
                for (int t = 1; t < j; t++) acc = f2fma(L2[IL(i, t)], L2[IL(j, t)], acc);
                v2 = f2fma(acc, NEG1, v2);
            }
            L2[IL(i, j)] = f2mul(v2, iv2[j]);
        }
    }

    // unpack to scalars for the asymmetric solve phases
    float Lx[21], Ly[21], ivx[6], ivy[6], xm[6], ym[6];
#pragma unroll
    for (int t = 0; t < 21; t++) f2up(L2[t], Lx[t], Ly[t]);
#pragma unroll
    for (int i = 0; i < 6; i++) {
        f2up(iv2[i], ivx[i], ivy[i]);
        f2up(m2[i], xm[i], ym[i]);
    }

    // cxy(i,j) raw-sum accessor
    auto sxy_at = [&](int i, int j) -> float {
        if (i == j) return sd[i];
        float lo, hi;
        if (i < j) { f2up(s2c[IP(i, j)], lo, hi); return lo; }
        f2up(s2c[IP(j, i)], lo, hi);
        return hi;
    };

    // M = Lx^{-1} * cxy ; only upper triangle (i<=j) needed downstream.
    float MN[21];
#pragma unroll
    for (int j = 0; j < 6; j++) {
#pragma unroll
        for (int i = 0; i <= j; i++) {
            float v = fmaf(-xm[i], ym[j], sxy_at(i, j) * inv_n);
#pragma unroll
            for (int t = 0; t < i; t++) v = fmaf(-Lx[IL(i, t)], MN[IU(t, j)], v);
            MN[IU(i, j)] = v * ivx[i];
        }
    }
    // N = M * Ly^{-1}, in place (back-substitution per row).
    float sim = 0.f;
#pragma unroll
    for (int i = 0; i < 6; i++) {
#pragma unroll
        for (int j = 5; j >= i; j--) {
            float v = MN[IU(i, j)];
#pragma unroll
            for (int t = j + 1; t < 6; t++) v = fmaf(-MN[IU(i, t)], Ly[IL(t, j)], v);
            v *= ivy[j];
            MN[IU(i, j)] = v;
            if (j == i) sim += fabsf(v);
        }
    }
    return sim * (1.0f / 6.0f);
}

// K = window size (2r+1), TILE = output tile side, NTX = column groups per row.
// Shared tile packs (x_c, y_c) as float2 per channel plane; window moments are
// accumulated with packed f32x2 FMA (x-lane and y-lane moments per instruction).
template <int K, int TILE, int NTX>
__global__ __launch_bounds__(TILE* NTX, 2) void cca_kernel(
    const float* __restrict__ x, const float* __restrict__ y,
    float* __restrict__ out, int ri) {
    constexpr int R = (K - 1) / 2;
    constexpr int PH = TILE + K - 1;
    constexpr int PW = TILE + K - 1;
    constexpr int PS = PW + 1;  // odd stride
    constexpr int RPP = TILE / NTX;
    constexpr float INV_N = 1.0f / (float)(K * K);

    extern __shared__ float2 sm[];  // [6][PH][PS] of (x,y)
    const ull* smu = (const ull*)sm;

    const int b = blockIdx.z;
    const int tx0 = blockIdx.x * TILE;
    const int ty0 = blockIdx.y * TILE;
    const int tid = threadIdx.x;

    // cooperative load of padded 6-channel (x,y)-packed tile
    for (int idx = tid; idx < 6 * PH * PW; idx += TILE * NTX) {
        int c = idx / (PH * PW);
        int rem = idx - c * (PH * PW);
        int row = rem / PW;
        int col = rem - row * PW;
        int gy = refl(ty0 - R + row, HH);
        int gx = refl(tx0 - R + col, WW);
        size_t gidx = ((size_t)(b * CHN + c) * HH + gy) * WW + gx;
        float2 v;
        v.x = x[gidx];
        v.y = y[gidx];
        sm[(c * PH + row) * PS + col] = v;
    }
    __syncthreads();

    const int txg = tid & (NTX - 1);
    const int ty = tid / NTX;      // output row within tile
    const int c0 = txg * RPP;      // first output col within tile

    const ull NEG1 = NEG1_F2;

    ull s2s[6], s2q[21], s2c[15];
    float sd[6];
#pragma unroll
    for (int i = 0; i < 6; i++) { s2s[i] = 0ULL; sd[i] = 0.f; }
#pragma unroll
    for (int i = 0; i < 21; i++) s2q[i] = 0ULL;
#pragma unroll
    for (int i = 0; i < 15; i++) s2c[i] = 0ULL;

    // ADD=true accumulates +point, ADD=false accumulates -point.
    auto accum = [&](int row, int col, bool add) {
        ull v[6];
#pragma unroll
        for (int c = 0; c < 6; c++) v[c] = smu[(c * PH + row) * PS + col];
        // swapped copies for sxy off-diagonal
        ull w[6];
#pragma unroll
        for (int c = 1; c < 6; c++) w[c] = f2swap(v[c]);
        // first operands (negated for subtraction)
        ull a[6];
        if (add) {
#pragma unroll
            for (int c = 0; c < 6; c++) a[c] = v[c];
        } else {
#pragma unroll
            for (int c = 0; c < 6; c++) a[c] = f2mul(v[c], NEG1);
        }
        // sums
#pragma unroll
        for (int c = 0; c < 6; c++) s2s[c] = f2fma(a[c], f2pk(1.0f, 1.0f), s2s[c]);
        // (sxx, syy)
        int t = 0;
#pragma unroll
        for (int i = 0; i < 6; i++)
#pragma unroll
            for (int j = i; j < 6; j++, t++) s2q[t] = f2fma(a[i], v[j], s2q[t]);
        // sxy off-diagonal pairs
#pragma unroll
        for (int i = 0; i < 6; i++)
#pragma unroll
            for (int j = i + 1; j < 6; j++) s2c[IP(i, j)] = f2fma(a[i], w[j], s2c[IP(i, j)]);
        // sxy diagonal (scalar)
#pragma unroll
        for (int i = 0; i < 6; i++) {
            float xs, ys;
            f2up(v[i], xs, ys);
            sd[i] = add ? fmaf(xs, ys, sd[i]) : fmaf(-xs, ys, sd[i]);
        }
    };

    // initial full window for first pixel
#pragma unroll 1
    for (int r = 0; r < K; ++r)
#pragma unroll 1
        for (int c = 0; c < K; ++c) accum(ty + r, c0 + c, true);

    const int gy = ty0 + ty;
    {
        float sim = cca6(s2s, s2q, s2c, sd, INV_N);
        out[(((size_t)b * HH + gy) * WW + (tx0 + c0)) * 2 + ri] = sim;
    }

#pragma unroll 1
    for (int p = 1; p < RPP; ++p) {
#pragma unroll 1
        for (int r = 0; r < K; ++r) {
            accum(ty + r, c0 + p - 1, false);
            accum(ty + r, c0 + p - 1 + K, true);
        }
        float sim = cca6(s2s, s2q, s2c, sd, INV_N);
        out[(((size_t)b * HH + gy) * WW + (tx0 + c0 + p)) * 2 + ri] = sim;
    }
}

extern "C" void kernel_launch(void* const* d_in, const int* in_sizes, int n_in,
                              void* d_out, int out_size) {
    (void)in_sizes; (void)n_in; (void)out_size;
    const float* x = (const float*)d_in[0];
    const float* y = (const float*)d_in[1];
    float* out = (float*)d_out;

    constexpr int TILE = 32, NTX = 8;
    dim3 grid(WW / TILE, HH / TILE, BATCH);
    dim3 block(TILE * NTX);

    // r=2 -> K=5: 6 planes of 36x37 float2
    constexpr int SM5 = 6 * 36 * 37 * 8;
    // r=4 -> K=9: 6 planes of 40x41 float2
    constexpr int SM9 = 6 * 40 * 41 * 8;

    cudaFuncSetAttribute(cca_kernel<5, TILE, NTX>,
                         cudaFuncAttributeMaxDynamicSharedMemorySize, SM5);
    cudaFuncSetAttribute(cca_kernel<9, TILE, NTX>,
                         cudaFuncAttributeMaxDynamicSharedMemorySize, SM9);

    cca_kernel<5, TILE, NTX><<<grid, block, SM5>>>(x, y, out, 0);
    cca_kernel<9, TILE, NTX><<<grid, block, SM9>>>(x, y, out, 1);
}

// round 7
// speedup vs baseline: 1.1028x; 1.1028x over previous
#include <cuda_runtime.h>

#define HH 512
#define WW 512
#define CHN 6
#define BATCH 2
#define EPS_F 1e-6f

__device__ __forceinline__ int refl(int i, int n) {
    if (i < 0) i = -i;
    if (i >= n) i = 2 * n - 2 - i;
    return i;
}

// upper-triangle (i<=j) linear index into 21-entry array
__device__ __forceinline__ constexpr int IU(int i, int j) {
    return i * 6 - i * (i - 1) / 2 + (j - i);
}
// lower-triangle (i>=j) linear index into 21-entry array
__device__ __forceinline__ constexpr int IL(int i, int j) {
    return i * (i + 1) / 2 + j;
}

// Per-pixel CCA directly from raw window sums. Covariance entries are
// materialized inline at their single use (no cxx/cyy/cxy register arrays).
// sxx/syy upper-tri (i<=j), sxy full row-major [i*6+j].
__device__ __forceinline__ float cca6(const float* sx, const float* sy,
                                      const float* sxx, const float* syy,
                                      const float* sxy, float inv_n) {
    float xm[6], ym[6];
#pragma unroll
    for (int i = 0; i < 6; i++) { xm[i] = sx[i] * inv_n; ym[i] = sy[i] * inv_n; }

    // Cholesky of cxx and cyy (lower L, 21 entries each); rsqrt-based.
    float Lx[21], Ly[21], ivx[6], ivy[6];
#pragma unroll
    for (int j = 0; j < 6; j++) {
        float dx = fmaf(-xm[j], xm[j], sxx[IU(j, j)] * inv_n) + EPS_F;
        float dy = fmaf(-ym[j], ym[j], syy[IU(j, j)] * inv_n) + EPS_F;
#pragma unroll
        for (int t = 0; t < j; t++) {
            dx = fmaf(-Lx[IL(j, t)], Lx[IL(j, t)], dx);
            dy = fmaf(-Ly[IL(j, t)], Ly[IL(j, t)], dy);
        }
        float rx = rsqrtf(dx), ry = rsqrtf(dy);
        ivx[j] = rx;
        ivy[j] = ry;
        Lx[IL(j, j)] = dx * rx;
        Ly[IL(j, j)] = dy * ry;
#pragma unroll
        for (int i = j + 1; i < 6; i++) {
            float vx = fmaf(-xm[j], xm[i], sxx[IU(j, i)] * inv_n);
            float vy = fmaf(-ym[j], ym[i], syy[IU(j, i)] * inv_n);
#pragma unroll
            for (int t = 0; t < j; t++) {
                vx = fmaf(-Lx[IL(i, t)], Lx[IL(j, t)], vx);
                vy = fmaf(-Ly[IL(i, t)], Ly[IL(j, t)], vy);
            }
            Lx[IL(i, j)] = vx * ivx[j];
            Ly[IL(i, j)] = vy * ivy[j];
        }
    }

    // M = Lx^{-1} * cxy ; only upper triangle (i<=j) needed downstream.
    float MN[21];
#pragma unroll
    for (int j = 0; j < 6; j++) {
#pragma unroll
        for (int i = 0; i <= j; i++) {
            float v = fmaf(-xm[i], ym[j], sxy[i * 6 + j] * inv_n);
#pragma unroll
            for (int t = 0; t < i; t++) v = fmaf(-Lx[IL(i, t)], MN[IU(t, j)], v);
            MN[IU(i, j)] = v * ivx[i];
        }
    }
    // N = M * Ly^{-1}, in place (back-substitution per row).
    float sim = 0.f;
#pragma unroll
    for (int i = 0; i < 6; i++) {
#pragma unroll
        for (int j = 5; j >= i; j--) {
            float v = MN[IU(i, j)];
#pragma unroll
            for (int t = j + 1; t < 6; t++) v = fmaf(-MN[IU(i, t)], Ly[IL(t, j)], v);
            v *= ivy[j];
            MN[IU(i, j)] = v;
            if (j == i) sim += fabsf(v);
        }
    }
    return sim * (1.0f / 6.0f);
}

// Single merged kernel: blockIdx.z encodes (batch, radius-index).
// ri=0 -> K=5, ri=1 -> K=9 (runtime K; channel loops stay compile-unrolled).
// Shared tile packs (x_c, y_c) as float2 per channel plane.
template <int TILE, int NTX>
__global__ __launch_bounds__(TILE* NTX, 2) void cca_kernel(
    const float* __restrict__ x, const float* __restrict__ y,
    float* __restrict__ out) {
    constexpr int PS = 41;            // max padded width (K=9) + 1, shared by both K
    constexpr int RPP = TILE / NTX;

    const int z = blockIdx.z;
    const int ri = z & 1;
    const int b = z >> 1;
    const int K = ri ? 9 : 5;
    const int R = (K - 1) >> 1;
    const int PH = TILE + K - 1;
    const int PW = PH;
    const float INV_N = 1.0f / (float)(K * K);
    const int chs = PH * PS;          // channel stride in float2 elements

    extern __shared__ float2 sm[];    // [6][PH][PS] of (x,y)

    const int tx0 = blockIdx.x * TILE;
    const int ty0 = blockIdx.y * TILE;
    const int tid = threadIdx.x;

    // cooperative load of padded 6-channel (x,y)-packed tile
    for (int idx = tid; idx < 6 * PH * PW; idx += TILE * NTX) {
        int c = idx / (PH * PW);
        int rem = idx - c * (PH * PW);
        int row = rem / PW;
        int col = rem - row * PW;
        int gy = refl(ty0 - R + row, HH);
        int gx = refl(tx0 - R + col, WW);
        size_t gidx = ((size_t)(b * CHN + c) * HH + gy) * WW + gx;
        float2 v;
        v.x = x[gidx];
        v.y = y[gidx];
        sm[c * chs + row * PS + col] = v;
    }
    __syncthreads();

    const int txg = tid & (NTX - 1);
    const int ty = tid / NTX;      // output row within tile
    const int c0 = txg * RPP;      // first output col within tile

    float sx[6], sy[6], sxx[21], syy[21], sxy[36];
#pragma unroll
    for (int i = 0; i < 6; i++) { sx[i] = 0.f; sy[i] = 0.f; }
#pragma unroll
    for (int i = 0; i < 21; i++) { sxx[i] = 0.f; syy[i] = 0.f; }
#pragma unroll
    for (int i = 0; i < 36; i++) sxy[i] = 0.f;

    auto loadvals = [&](int row, int col, float* xv, float* yv) {
        const float2* p = sm + row * PS + col;
#pragma unroll
        for (int c = 0; c < 6; c++) {
            float2 v = p[c * chs];
            xv[c] = v.x;
            yv[c] = v.y;
        }
    };
    auto accumAdd = [&](int row, int col) {
        float xv[6], yv[6];
        loadvals(row, col, xv, yv);
#pragma unroll
        for (int i = 0; i < 6; i++) { sx[i] += xv[i]; sy[i] += yv[i]; }
        int t = 0;
#pragma unroll
        for (int i = 0; i < 6; i++)
#pragma unroll
            for (int j = i; j < 6; j++, t++) {
                sxx[t] = fmaf(xv[i], xv[j], sxx[t]);
                syy[t] = fmaf(yv[i], yv[j], syy[t]);
            }
#pragma unroll
        for (int i = 0; i < 6; i++)
#pragma unroll
            for (int j = 0; j < 6; j++)
                sxy[i * 6 + j] = fmaf(xv[i], yv[j], sxy[i * 6 + j]);
    };
    auto accumSub = [&](int row, int col) {
        float xv[6], yv[6];
        loadvals(row, col, xv, yv);
#pragma unroll
        for (int i = 0; i < 6; i++) { sx[i] -= xv[i]; sy[i] -= yv[i]; }
        int t = 0;
#pragma unroll
        for (int i = 0; i < 6; i++)
#pragma unroll
            for (int j = i; j < 6; j++, t++) {
                sxx[t] = fmaf(-xv[i], xv[j], sxx[t]);
                syy[t] = fmaf(-yv[i], yv[j], syy[t]);
            }
#pragma unroll
        for (int i = 0; i < 6; i++)
#pragma unroll
            for (int j = 0; j < 6; j++)
                sxy[i * 6 + j] = fmaf(-xv[i], yv[j], sxy[i * 6 + j]);
    };

    // initial full window for first pixel
#pragma unroll 1
    for (int r = 0; r < K; ++r)
#pragma unroll 1
        for (int c = 0; c < K; ++c) accumAdd(ty + r, c0 + c);

    const int gy = ty0 + ty;
    {
        float sim = cca6(sx, sy, sxx, syy, sxy, INV_N);
        out[(((size_t)b * HH + gy) * WW + (tx0 + c0)) * 2 + ri] = sim;
    }

#pragma unroll 1
    for (int p = 1; p < RPP; ++p) {
#pragma unroll 1
        for (int r = 0; r < K; ++r) {
            accumSub(ty + r, c0 + p - 1);
            accumAdd(ty + r, c0 + p - 1 + K);
        }
        float sim = cca6(sx, sy, sxx, syy, sxy, INV_N);
        out[(((size_t)b * HH + gy) * WW + (tx0 + c0 + p)) * 2 + ri] = sim;
    }
}

extern "C" void kernel_launch(void* const* d_in, const int* in_sizes, int n_in,
                              void* d_out, int out_size) {
    (void)in_sizes; (void)n_in; (void)out_size;
    const float* x = (const float*)d_in[0];
    const float* y = (const float*)d_in[1];
    float* out = (float*)d_out;

    constexpr int TILE = 32, NTX = 8;
    // grid.z = BATCH * 2 radii; z&1 = radius index, z>>1 = batch
    dim3 grid(WW / TILE, HH / TILE, BATCH * 2);
    dim3 block(TILE * NTX);

    // max smem (K=9): 6 planes of 40x41 float2
    constexpr int SMX = 6 * 40 * 41 * 8;

    cudaFuncSetAttribute(cca_kernel<TILE, NTX>,
                         cudaFuncAttributeMaxDynamicSharedMemorySize, SMX);

    cca_kernel<TILE, NTX><<<grid, block, SMX>>>(x, y, out);
}

// round 8
// speedup vs baseline: 1.2292x; 1.1146x over previous
#include <cuda_runtime.h>

#define HH 512
#define WW 512
#define CHN 6
#define BATCH 2
#define EPS_F 1e-6f

__device__ __forceinline__ int refl(int i, int n) {
    if (i < 0) i = -i;
    if (i >= n) i = 2 * n - 2 - i;
    return i;
}

// upper-triangle (i<=j) linear index into 21-entry array
__device__ __forceinline__ constexpr int IU(int i, int j) {
    return i * 6 - i * (i - 1) / 2 + (j - i);
}
// lower-triangle (i>=j) linear index into 21-entry array
__device__ __forceinline__ constexpr int IL(int i, int j) {
    return i * (i + 1) / 2 + j;
}

// Per-pixel CCA directly from raw window sums. Covariance entries are
// materialized inline at their single use (no cxx/cyy/cxy register arrays).
// sxx/syy upper-tri (i<=j), sxy full row-major [i*6+j].
__device__ __forceinline__ float cca6(const float* sx, const float* sy,
                                      const float* sxx, const float* syy,
                                      const float* sxy, float inv_n) {
    float xm[6], ym[6];
#pragma unroll
    for (int i = 0; i < 6; i++) { xm[i] = sx[i] * inv_n; ym[i] = sy[i] * inv_n; }

    // Cholesky of cxx and cyy (lower L, 21 entries each); rsqrt-based.
    float Lx[21], Ly[21], ivx[6], ivy[6];
#pragma unroll
    for (int j = 0; j < 6; j++) {
        float dx = fmaf(-xm[j], xm[j], sxx[IU(j, j)] * inv_n) + EPS_F;
        float dy = fmaf(-ym[j], ym[j], syy[IU(j, j)] * inv_n) + EPS_F;
#pragma unroll
        for (int t = 0; t < j; t++) {
            dx = fmaf(-Lx[IL(j, t)], Lx[IL(j, t)], dx);
            dy = fmaf(-Ly[IL(j, t)], Ly[IL(j, t)], dy);
        }
        float rx = rsqrtf(dx), ry = rsqrtf(dy);
        ivx[j] = rx;
        ivy[j] = ry;
        Lx[IL(j, j)] = dx * rx;
        Ly[IL(j, j)] = dy * ry;
#pragma unroll
        for (int i = j + 1; i < 6; i++) {
            float vx = fmaf(-xm[j], xm[i], sxx[IU(j, i)] * inv_n);
            float vy = fmaf(-ym[j], ym[i], syy[IU(j, i)] * inv_n);
#pragma unroll
            for (int t = 0; t < j; t++) {
                vx = fmaf(-Lx[IL(i, t)], Lx[IL(j, t)], vx);
                vy = fmaf(-Ly[IL(i, t)], Ly[IL(j, t)], vy);
            }
            Lx[IL(i, j)] = vx * ivx[j];
            Ly[IL(i, j)] = vy * ivy[j];
        }
    }

    // M = Lx^{-1} * cxy ; only upper triangle (i<=j) needed downstream.
    float MN[21];
#pragma unroll
    for (int j = 0; j < 6; j++) {
#pragma unroll
        for (int i = 0; i <= j; i++) {
            float v = fmaf(-xm[i], ym[j], sxy[i * 6 + j] * inv_n);
#pragma unroll
            for (int t = 0; t < i; t++) v = fmaf(-Lx[IL(i, t)], MN[IU(t, j)], v);
            MN[IU(i, j)] = v * ivx[i];
        }
    }
    // N = M * Ly^{-1}, in place (back-substitution per row).
    float sim = 0.f;
#pragma unroll
    for (int i = 0; i < 6; i++) {
#pragma unroll
        for (int j = 5; j >= i; j--) {
            float v = MN[IU(i, j)];
#pragma unroll
            for (int t = j + 1; t < 6; t++) v = fmaf(-MN[IU(i, t)], Ly[IL(t, j)], v);
            v *= ivy[j];
            MN[IU(i, j)] = v;
            if (j == i) sim += fabsf(v);
        }
    }
    return sim * (1.0f / 6.0f);
}

// Compile-time-K body. All plane strides constexpr -> LDS immediate offsets.
template <int K, int TILE, int NTX>
__device__ __forceinline__ void cca_body(
    const float* __restrict__ x, const float* __restrict__ y,
    float* __restrict__ out, int b, int ri, float2* sm) {
    constexpr int R = (K - 1) / 2;
    constexpr int PH = TILE + K - 1;
    constexpr int PW = PH;
    constexpr int PS = PW + 1;   // odd stride -> conflict-free
    constexpr int CHS = PH * PS; // channel stride (float2 elems), constexpr
    constexpr int RPP = TILE / NTX;
    constexpr float INV_N = 1.0f / (float)(K * K);

    const int tx0 = blockIdx.x * TILE;
    const int ty0 = blockIdx.y * TILE;
    const int tid = threadIdx.x;

    // cooperative load of padded 6-channel (x,y)-packed tile
    for (int idx = tid; idx < 6 * PH * PW; idx += TILE * NTX) {
        int c = idx / (PH * PW);
        int rem = idx - c * (PH * PW);
        int row = rem / PW;
        int col = rem - row * PW;
        int gy = refl(ty0 - R + row, HH);
        int gx = refl(tx0 - R + col, WW);
        size_t gidx = ((size_t)(b * CHN + c) * HH + gy) * WW + gx;
        float2 v;
        v.x = x[gidx];
        v.y = y[gidx];
        sm[c * CHS + row * PS + col] = v;
    }
    __syncthreads();

    const int txg = tid & (NTX - 1);
    const int ty = tid / NTX;      // output row within tile
    const int c0 = txg * RPP;      // first output col within tile

    float sx[6], sy[6], sxx[21], syy[21], sxy[36];
#pragma unroll
    for (int i = 0; i < 6; i++) { sx[i] = 0.f; sy[i] = 0.f; }
#pragma unroll
    for (int i = 0; i < 21; i++) { sxx[i] = 0.f; syy[i] = 0.f; }
#pragma unroll
    for (int i = 0; i < 36; i++) sxy[i] = 0.f;

    auto loadvals = [&](int row, int col, float* xv, float* yv) {
        const float2* p = sm + row * PS + col;
#pragma unroll
        for (int c = 0; c < 6; c++) {
            float2 v = p[c * CHS];  // constexpr offset -> LDS immediate
            xv[c] = v.x;
            yv[c] = v.y;
        }
    };
    auto accumAdd = [&](int row, int col) {
        float xv[6], yv[6];
        loadvals(row, col, xv, yv);
#pragma unroll
        for (int i = 0; i < 6; i++) { sx[i] += xv[i]; sy[i] += yv[i]; }
        int t = 0;
#pragma unroll
        for (int i = 0; i < 6; i++)
#pragma unroll
            for (int j = i; j < 6; j++, t++) {
                sxx[t] = fmaf(xv[i], xv[j], sxx[t]);
                syy[t] = fmaf(yv[i], yv[j], syy[t]);
            }
#pragma unroll
        for (int i = 0; i < 6; i++)
#pragma unroll
            for (int j = 0; j < 6; j++)
                sxy[i * 6 + j] = fmaf(xv[i], yv[j], sxy[i * 6 + j]);
    };
    auto accumSub = [&](int row, int col) {
        float xv[6], yv[6];
        loadvals(row, col, xv, yv);
#pragma unroll
        for (int i = 0; i < 6; i++) { sx[i] -= xv[i]; sy[i] -= yv[i]; }
        int t = 0;
#pragma unroll
        for (int i = 0; i < 6; i++)
#pragma unroll
            for (int j = i; j < 6; j++, t++) {
                sxx[t] = fmaf(-xv[i], xv[j], sxx[t]);
                syy[t] = fmaf(-yv[i], yv[j], syy[t]);
            }
#pragma unroll
        for (int i = 0; i < 6; i++)
#pragma unroll
            for (int j = 0; j < 6; j++)
                sxy[i * 6 + j] = fmaf(-xv[i], yv[j], sxy[i * 6 + j]);
    };

    // initial full window for first pixel
#pragma unroll 1
    for (int r = 0; r < K; ++r)
#pragma unroll 1
        for (int c = 0; c < K; ++c) accumAdd(ty + r, c0 + c);

    const int gy = ty0 + ty;
    {
        float sim = cca6(sx, sy, sxx, syy, sxy, INV_N);
        out[(((size_t)b * HH + gy) * WW + (tx0 + c0)) * 2 + ri] = sim;
    }

#pragma unroll 1
    for (int p = 1; p < RPP; ++p) {
#pragma unroll 1
        for (int r = 0; r < K; ++r) {
            accumSub(ty + r, c0 + p - 1);
            accumAdd(ty + r, c0 + p - 1 + K);
        }
        float sim = cca6(sx, sy, sxx, syy, sxy, INV_N);
        out[(((size_t)b * HH + gy) * WW + (tx0 + c0 + p)) * 2 + ri] = sim;
    }
}

// Single merged launch; blockIdx.z encodes (batch, radius). Uniform per-CTA
// branch dispatches to a compile-time-K body.
template <int TILE, int NTX>
__global__ __launch_bounds__(TILE* NTX, 2) void cca_kernel(
    const float* __restrict__ x, const float* __restrict__ y,
    float* __restrict__ out) {
    extern __shared__ float2 sm[];
    const int z = blockIdx.z;
    const int ri = z & 1;
    const int b = z >> 1;
    if (ri == 0)
        cca_body<5, TILE, NTX>(x, y, out, b, 0, sm);
    else
        cca_body<9, TILE, NTX>(x, y, out, b, 1, sm);
}

extern "C" void kernel_launch(void* const* d_in, const int* in_sizes, int n_in,
                              void* d_out, int out_size) {
    (void)in_sizes; (void)n_in; (void)out_size;
    const float* x = (const float*)d_in[0];
    const float* y = (const float*)d_in[1];
    float* out = (float*)d_out;

    constexpr int TILE = 32, NTX = 8;
    dim3 grid(WW / TILE, HH / TILE, BATCH * 2);
    dim3 block(TILE * NTX);

    // max smem (K=9): 6 planes of 40x41 float2
    constexpr int SMX = 6 * 40 * 41 * 8;

    cudaFuncSetAttribute(cca_kernel<TILE, NTX>,
                         cudaFuncAttributeMaxDynamicSharedMemorySize, SMX);

    cca_kernel<TILE, NTX><<<grid, block, SMX>>>(x, y, out);
}